// round 5
// baseline (speedup 1.0000x reference)
#include <cuda_runtime.h>
#include <cstdint>

// Problem constants
#define B_ROWS   65536
#define K1       1024
#define K2       512
#define K3       768
#define NPAIRS   1152                  // (K1+K2+K3)/2
#define RANK     10
#define OUTDIM   512

// ---- kernel 1 (rank projection) ----
#define T1       256
#define GRID1    304                   // 2 CTAs/SM
#define NWARPS   (GRID1 * (T1 / 32))   // 2432
#define NGROUPS  (B_ROWS / 4)          // 16384 groups of 4 rows

#define FS_ELEMS (RANK * NPAIRS)       // 11520 float2
#define SMEM1    (FS_ELEMS * 8)        // 92160 B

// ---- kernel 2 (out = y @ fout^T) ----
#define T2       512
#define RTILE    128
#define GRID2    (B_ROWS / RTILE)      // 512

typedef unsigned long long u64;

// scratch for the intermediate y[B, RANK]
__device__ float y_buf[(size_t)B_ROWS * RANK];

// ---------- f32x2 packed helpers ----------
__device__ __forceinline__ u64 pk2(float lo, float hi) {
    u64 r; asm("mov.b64 %0, {%1, %2};" : "=l"(r) : "f"(lo), "f"(hi)); return r;
}
__device__ __forceinline__ void upk2(u64 v, float& lo, float& hi) {
    asm("mov.b64 {%0, %1}, %2;" : "=f"(lo), "=f"(hi) : "l"(v));
}
__device__ __forceinline__ u64 fma2(u64 a, u64 b, u64 c) {
    u64 d; asm("fma.rn.f32x2 %0, %1, %2, %3;" : "=l"(d) : "l"(a), "l"(b), "l"(c));
    return d;
}
__device__ __forceinline__ float hadd2(u64 v) {
    float lo, hi; upk2(v, lo, hi); return lo + hi;
}

// One segment, 4 rows per warp.
// Half-warp h (lane>>4) owns ranks h*5..h*5+4; the 16 lanes of each half
// cover the k dimension (lane kL handles floats c*64 + kL*4 .. +3 per chunk).
// Both halves read identical x addresses -> coalescer merges them.
// Output: z[i][j] = full dot for row i, rank h*5+j (all lanes of the half
// hold it after the 16-lane butterfly).
template<int KSEG, int PAIR_OFF>
__device__ __forceinline__ void segment4(
    const float* __restrict__ x, int row0, int kL, int h,
    const ulonglong2* __restrict__ f2, float z[4][5])
{
    constexpr int NC = KSEG / 64;     // 64-float chunks

    u64 acc[4][5];
#pragma unroll
    for (int i = 0; i < 4; i++)
#pragma unroll
        for (int j = 0; j < 5; j++) acc[i][j] = 0ull;

    const float4* q0 = reinterpret_cast<const float4*>(x + (size_t)(row0    ) * KSEG) + kL;
    const float4* q1 = reinterpret_cast<const float4*>(x + (size_t)(row0 + 1) * KSEG) + kL;
    const float4* q2 = reinterpret_cast<const float4*>(x + (size_t)(row0 + 2) * KSEG) + kL;
    const float4* q3 = reinterpret_cast<const float4*>(x + (size_t)(row0 + 3) * KSEG) + kL;

    float4 A0 = q0[0], A1 = q1[0], A2 = q2[0], A3 = q3[0];

    // factor base index in ulonglong2 units for rank h*5, this segment, this lane
    const int fb = (h * 5 * NPAIRS + PAIR_OFF) / 2 + kL;

#pragma unroll 2
    for (int c = 0; c < NC; c++) {
        float4 B0, B1, B2, B3;
        if (c + 1 < NC) {                      // prefetch next chunk
            B0 = q0[(c + 1) * 16];
            B1 = q1[(c + 1) * 16];
            B2 = q2[(c + 1) * 16];
            B3 = q3[(c + 1) * 16];
        }
        u64 x00 = pk2(A0.x, A0.y), x01 = pk2(A0.z, A0.w);
        u64 x10 = pk2(A1.x, A1.y), x11 = pk2(A1.z, A1.w);
        u64 x20 = pk2(A2.x, A2.y), x21 = pk2(A2.z, A2.w);
        u64 x30 = pk2(A3.x, A3.y), x31 = pk2(A3.z, A3.w);

        const ulonglong2* fp = f2 + fb + c * 16;
#pragma unroll
        for (int j = 0; j < 5; j++) {
            ulonglong2 fv = fp[j * (NPAIRS / 2)];   // LDS.128, per-half contiguous
            acc[0][j] = fma2(x00, fv.x, acc[0][j]);
            acc[0][j] = fma2(x01, fv.y, acc[0][j]);
            acc[1][j] = fma2(x10, fv.x, acc[1][j]);
            acc[1][j] = fma2(x11, fv.y, acc[1][j]);
            acc[2][j] = fma2(x20, fv.x, acc[2][j]);
            acc[2][j] = fma2(x21, fv.y, acc[2][j]);
            acc[3][j] = fma2(x30, fv.x, acc[3][j]);
            acc[3][j] = fma2(x31, fv.y, acc[3][j]);
        }
        A0 = B0; A1 = B1; A2 = B2; A3 = B3;
    }

    // fold even/odd halves, then butterfly over the 16-lane k-group
#pragma unroll
    for (int i = 0; i < 4; i++)
#pragma unroll
        for (int j = 0; j < 5; j++) z[i][j] = hadd2(acc[i][j]);

#pragma unroll
    for (int m = 8; m > 0; m >>= 1) {
#pragma unroll
        for (int i = 0; i < 4; i++)
#pragma unroll
            for (int j = 0; j < 5; j++)
                z[i][j] += __shfl_xor_sync(0xffffffffu, z[i][j], m);
    }
}

extern "C" __global__ void __launch_bounds__(T1, 2)
arf_k1(const float* __restrict__ x1, const float* __restrict__ x2,
       const float* __restrict__ x3,
       const float* __restrict__ f1, const float* __restrict__ f2g,
       const float* __restrict__ f3)
{
    extern __shared__ float2 f_s[];    // [RANK][NPAIRS], k-pair packed

    const int tid = threadIdx.x;

    // factor repack: f_s[r*NPAIRS + kp] = (f_seg[2k][r], f_seg[2k+1][r])
    for (int idx = tid; idx < FS_ELEMS; idx += T1) {
        int r  = idx / NPAIRS;
        int kp = idx % NPAIRS;
        const float* f; int kloc;
        if (kp < K1 / 2)              { f = f1;  kloc = 2 * kp; }
        else if (kp < (K1 + K2) / 2)  { f = f2g; kloc = 2 * (kp - K1 / 2); }
        else                          { f = f3;  kloc = 2 * (kp - (K1 + K2) / 2); }
        f_s[idx] = make_float2(f[kloc * RANK + r], f[(kloc + 1) * RANK + r]);
    }
    __syncthreads();

    const ulonglong2* fsp = reinterpret_cast<const ulonglong2*>(f_s);

    const int lane = tid & 31;
    const int kL   = lane & 15;
    const int h    = lane >> 4;
    const int gw   = (blockIdx.x * T1 + tid) >> 5;

    for (int g = gw; g < NGROUPS; g += NWARPS) {
        const int row0 = g * 4;

        float z1[4][5], zt[4][5];

        segment4<K1, 0>            (x1, row0, kL, h, fsp, z1);
        segment4<K2, K1 / 2>       (x2, row0, kL, h, fsp, zt);
#pragma unroll
        for (int i = 0; i < 4; i++)
#pragma unroll
            for (int j = 0; j < 5; j++) z1[i][j] *= zt[i][j];
        segment4<K3, (K1 + K2) / 2>(x3, row0, kL, h, fsp, zt);
#pragma unroll
        for (int i = 0; i < 4; i++)
#pragma unroll
            for (int j = 0; j < 5; j++) z1[i][j] *= zt[i][j];

        // lanes kL<4 write: lane (h*16 + i) writes row row0+i, ranks h*5..h*5+4
#pragma unroll
        for (int i = 0; i < 4; i++) {
            if (kL == i) {
#pragma unroll
                for (int j = 0; j < 5; j++)
                    y_buf[(size_t)(row0 + i) * RANK + h * 5 + j] = z1[i][j];
            }
        }
    }
}

// out[b, c] = sum_j y[b, j] * fout[c, j]
// CTA: 512 threads = 512 cols; 128-row tile; y transposed in smem so a
// row-pair is one LDS.64 broadcast; fout lives in registers (packed dup).
extern "C" __global__ void __launch_bounds__(T2)
arf_k2(const float* __restrict__ fout, float* __restrict__ out)
{
    __shared__ float yt[RANK][RTILE];   // transposed y tile

    const int c    = threadIdx.x;
    const int base = blockIdx.x * RTILE;

    u64 fo[RANK];
#pragma unroll
    for (int j = 0; j < RANK; j++) {
        float v = fout[c * RANK + j];
        fo[j] = pk2(v, v);
    }

    for (int idx = c; idx < RTILE * RANK; idx += T2) {
        int r = idx / RANK, j = idx % RANK;       // coalesced y_buf read
        yt[j][r] = y_buf[(size_t)base * RANK + idx];
    }
    __syncthreads();

    for (int rp = 0; rp < RTILE / 2; rp++) {
        u64 acc = 0ull;
#pragma unroll
        for (int j = 0; j < RANK; j++) {
            u64 yv = *reinterpret_cast<const u64*>(&yt[j][2 * rp]);  // broadcast
            acc = fma2(yv, fo[j], acc);
        }
        float lo, hi; upk2(acc, lo, hi);
        out[(size_t)(base + 2 * rp    ) * OUTDIM + c] = lo;   // coalesced
        out[(size_t)(base + 2 * rp + 1) * OUTDIM + c] = hi;
    }
}

extern "C" void kernel_launch(void* const* d_in, const int* in_sizes, int n_in,
                              void* d_out, int out_size)
{
    const float* x1   = (const float*)d_in[0];
    const float* x2   = (const float*)d_in[1];
    const float* x3   = (const float*)d_in[2];
    const float* f1   = (const float*)d_in[3];
    const float* f2   = (const float*)d_in[4];
    const float* f3   = (const float*)d_in[5];
    const float* fout = (const float*)d_in[6];
    float* out = (float*)d_out;

    cudaFuncSetAttribute(arf_k1,
                         cudaFuncAttributeMaxDynamicSharedMemorySize, SMEM1);

    arf_k1<<<GRID1, T1, SMEM1>>>(x1, x2, x3, f1, f2, f3);
    arf_k2<<<GRID2, T2>>>(fout, out);
}

// round 6
// speedup vs baseline: 1.0843x; 1.0843x over previous
#include <cuda_runtime.h>
#include <cstdint>

// Problem constants
#define B_ROWS   65536
#define K1       1024
#define K2       512
#define K3       768
#define NPAIRS   1152                  // (K1+K2+K3)/2
#define RANK     10
#define OUTDIM   512

// ---- kernel 1 (rank projection) ----
#define T1       192
#define GRID1    304                   // 2 CTAs/SM
#define NWARPS   (GRID1 * (T1 / 32))   // 1824
#define NGROUPS  (B_ROWS / 4)          // 16384 groups of 4 rows

#define FS_ELEMS (RANK * NPAIRS)       // 11520 float2
#define SMEM1    (FS_ELEMS * 8)        // 92160 B

// ---- kernel 2 (out = y @ fout^T) ----
#define T2       256
#define RTILE    128
#define GRID2    (B_ROWS / RTILE)      // 512

typedef unsigned long long u64;

// scratch for the intermediate y[B, RANK]
__device__ float y_buf[(size_t)B_ROWS * RANK];

// ---------- f32x2 packed helpers ----------
__device__ __forceinline__ u64 pk2(float lo, float hi) {
    u64 r; asm("mov.b64 %0, {%1, %2};" : "=l"(r) : "f"(lo), "f"(hi)); return r;
}
__device__ __forceinline__ void upk2(u64 v, float& lo, float& hi) {
    asm("mov.b64 {%0, %1}, %2;" : "=f"(lo), "=f"(hi) : "l"(v));
}
__device__ __forceinline__ u64 fma2(u64 a, u64 b, u64 c) {
    u64 d; asm("fma.rn.f32x2 %0, %1, %2, %3;" : "=l"(d) : "l"(a), "l"(b), "l"(c));
    return d;
}
__device__ __forceinline__ float hadd2(u64 v) {
    float lo, hi; upk2(v, lo, hi); return lo + hi;
}

// One segment, 4 rows per warp, depth-2 software-pipelined x prefetch.
// Half-warp h (lane>>4) owns ranks h*5..h*5+4; the 16 lanes of each half
// cover the k dimension (lane kL handles floats c*64 + kL*4 .. +3 per chunk).
// x is loaded directly as ulonglong2 (two packed f32x2 operands, no movs).
template<int KSEG, int PAIR_OFF>
__device__ __forceinline__ void segment4(
    const float* __restrict__ x, int row0, int kL, int h,
    const ulonglong2* __restrict__ f2, float z[4][5])
{
    constexpr int NC = KSEG / 64;     // 64-float chunks
    static_assert(NC >= 2 && NC % 4 == 0, "chunk count");

    u64 acc[4][5];
#pragma unroll
    for (int i = 0; i < 4; i++)
#pragma unroll
        for (int j = 0; j < 5; j++) acc[i][j] = 0ull;

    const ulonglong2* q0 = reinterpret_cast<const ulonglong2*>(x + (size_t)(row0    ) * KSEG) + kL;
    const ulonglong2* q1 = reinterpret_cast<const ulonglong2*>(x + (size_t)(row0 + 1) * KSEG) + kL;
    const ulonglong2* q2 = reinterpret_cast<const ulonglong2*>(x + (size_t)(row0 + 2) * KSEG) + kL;
    const ulonglong2* q3 = reinterpret_cast<const ulonglong2*>(x + (size_t)(row0 + 3) * KSEG) + kL;

    // rotating 2-stage prefetch buffers
    ulonglong2 buf[2][4];
    buf[0][0] = q0[0];  buf[0][1] = q1[0];  buf[0][2] = q2[0];  buf[0][3] = q3[0];
    buf[1][0] = q0[16]; buf[1][1] = q1[16]; buf[1][2] = q2[16]; buf[1][3] = q3[16];

    // factor base index in ulonglong2 units for rank h*5, this segment, this lane
    const int fb = (h * 5 * NPAIRS + PAIR_OFF) / 2 + kL;

#pragma unroll 4
    for (int c = 0; c < NC; c++) {
        const int s = c & 1;
        ulonglong2 v0 = buf[s][0];
        ulonglong2 v1 = buf[s][1];
        ulonglong2 v2 = buf[s][2];
        ulonglong2 v3 = buf[s][3];
        if (c + 2 < NC) {                        // refill this stage, 2 ahead
            buf[s][0] = q0[(c + 2) * 16];
            buf[s][1] = q1[(c + 2) * 16];
            buf[s][2] = q2[(c + 2) * 16];
            buf[s][3] = q3[(c + 2) * 16];
        }

        const ulonglong2* fp = f2 + fb + c * 16;
#pragma unroll
        for (int j = 0; j < 5; j++) {
            ulonglong2 fv = fp[j * (NPAIRS / 2)];   // LDS.128, per-half contiguous
            acc[0][j] = fma2(v0.x, fv.x, acc[0][j]);
            acc[0][j] = fma2(v0.y, fv.y, acc[0][j]);
            acc[1][j] = fma2(v1.x, fv.x, acc[1][j]);
            acc[1][j] = fma2(v1.y, fv.y, acc[1][j]);
            acc[2][j] = fma2(v2.x, fv.x, acc[2][j]);
            acc[2][j] = fma2(v2.y, fv.y, acc[2][j]);
            acc[3][j] = fma2(v3.x, fv.x, acc[3][j]);
            acc[3][j] = fma2(v3.y, fv.y, acc[3][j]);
        }
    }

    // fold even/odd halves, then butterfly over the 16-lane k-group
#pragma unroll
    for (int i = 0; i < 4; i++)
#pragma unroll
        for (int j = 0; j < 5; j++) z[i][j] = hadd2(acc[i][j]);

#pragma unroll
    for (int m = 8; m > 0; m >>= 1) {
#pragma unroll
        for (int i = 0; i < 4; i++)
#pragma unroll
            for (int j = 0; j < 5; j++)
                z[i][j] += __shfl_xor_sync(0xffffffffu, z[i][j], m);
    }
}

extern "C" __global__ void __launch_bounds__(T1, 2)
arf_k1(const float* __restrict__ x1, const float* __restrict__ x2,
       const float* __restrict__ x3,
       const float* __restrict__ f1, const float* __restrict__ f2g,
       const float* __restrict__ f3)
{
    extern __shared__ float2 f_s[];    // [RANK][NPAIRS], k-pair packed

    const int tid = threadIdx.x;

    // factor repack: f_s[r*NPAIRS + kp] = (f_seg[2k][r], f_seg[2k+1][r])
    for (int idx = tid; idx < FS_ELEMS; idx += T1) {
        int r  = idx / NPAIRS;
        int kp = idx % NPAIRS;
        const float* f; int kloc;
        if (kp < K1 / 2)              { f = f1;  kloc = 2 * kp; }
        else if (kp < (K1 + K2) / 2)  { f = f2g; kloc = 2 * (kp - K1 / 2); }
        else                          { f = f3;  kloc = 2 * (kp - (K1 + K2) / 2); }
        f_s[idx] = make_float2(f[kloc * RANK + r], f[(kloc + 1) * RANK + r]);
    }
    __syncthreads();

    const ulonglong2* fsp = reinterpret_cast<const ulonglong2*>(f_s);

    const int lane = tid & 31;
    const int kL   = lane & 15;
    const int h    = lane >> 4;
    const int gw   = (blockIdx.x * T1 + tid) >> 5;

    for (int g = gw; g < NGROUPS; g += NWARPS) {
        const int row0 = g * 4;

        float z1[4][5], zt[4][5];

        segment4<K1, 0>            (x1, row0, kL, h, fsp, z1);
        segment4<K2, K1 / 2>       (x2, row0, kL, h, fsp, zt);
#pragma unroll
        for (int i = 0; i < 4; i++)
#pragma unroll
            for (int j = 0; j < 5; j++) z1[i][j] *= zt[i][j];
        segment4<K3, (K1 + K2) / 2>(x3, row0, kL, h, fsp, zt);
#pragma unroll
        for (int i = 0; i < 4; i++)
#pragma unroll
            for (int j = 0; j < 5; j++) z1[i][j] *= zt[i][j];

        // lane (h*16 + i) writes row row0+i, ranks h*5..h*5+4
#pragma unroll
        for (int i = 0; i < 4; i++) {
            if (kL == i) {
#pragma unroll
                for (int j = 0; j < 5; j++)
                    y_buf[(size_t)(row0 + i) * RANK + h * 5 + j] = z1[i][j];
            }
        }
    }
}

// out[b, c] = sum_j y[b, j] * fout[c, j]
// CTA: 256 threads, each owns cols c and c+256 (every yv LDS serves 4 outputs);
// 128-row tile; y transposed in smem so a row-pair is one LDS.64 broadcast;
// fout lives in registers (packed duplicate).
extern "C" __global__ void __launch_bounds__(T2)
arf_k2(const float* __restrict__ fout, float* __restrict__ out)
{
    __shared__ float yt[RANK][RTILE];   // transposed y tile

    const int c0   = threadIdx.x;
    const int c1   = c0 + 256;
    const int base = blockIdx.x * RTILE;

    u64 fo0[RANK], fo1[RANK];
#pragma unroll
    for (int j = 0; j < RANK; j++) {
        float v0 = fout[c0 * RANK + j];
        float v1 = fout[c1 * RANK + j];
        fo0[j] = pk2(v0, v0);
        fo1[j] = pk2(v1, v1);
    }

    for (int idx = c0; idx < RTILE * RANK; idx += T2) {
        int r = idx / RANK, j = idx % RANK;       // coalesced y_buf read
        yt[j][r] = y_buf[(size_t)base * RANK + idx];
    }
    __syncthreads();

#pragma unroll 4
    for (int rp = 0; rp < RTILE / 2; rp++) {
        u64 yv[RANK];
#pragma unroll
        for (int j = 0; j < RANK; j++)
            yv[j] = *reinterpret_cast<const u64*>(&yt[j][2 * rp]);  // broadcast

        u64 a0 = 0ull, a1 = 0ull;
#pragma unroll
        for (int j = 0; j < RANK; j++) {
            a0 = fma2(yv[j], fo0[j], a0);
            a1 = fma2(yv[j], fo1[j], a1);
        }
        float lo0, hi0, lo1, hi1;
        upk2(a0, lo0, hi0);
        upk2(a1, lo1, hi1);
        float* o0 = out + (size_t)(base + 2 * rp) * OUTDIM;
        o0[c0]           = lo0;      // coalesced
        o0[c1]           = lo1;
        o0[OUTDIM + c0]  = hi0;
        o0[OUTDIM + c1]  = hi1;
    }
}

extern "C" void kernel_launch(void* const* d_in, const int* in_sizes, int n_in,
                              void* d_out, int out_size)
{
    const float* x1   = (const float*)d_in[0];
    const float* x2   = (const float*)d_in[1];
    const float* x3   = (const float*)d_in[2];
    const float* f1   = (const float*)d_in[3];
    const float* f2   = (const float*)d_in[4];
    const float* f3   = (const float*)d_in[5];
    const float* fout = (const float*)d_in[6];
    float* out = (float*)d_out;

    cudaFuncSetAttribute(arf_k1,
                         cudaFuncAttributeMaxDynamicSharedMemorySize, SMEM1);

    arf_k1<<<GRID1, T1, SMEM1>>>(x1, x2, x3, f1, f2, f3);
    arf_k2<<<GRID2, T2>>>(fout, out);
}